// round 4
// baseline (speedup 1.0000x reference)
#include <cuda_runtime.h>

#define DIM    256
#define NQ     8
#define FFN    2048
#define EMBED  512
#define BS     32768            // B * S = 4 * 8192
#define OUT_F4 (BS * EMBED / 4) // 4,194,304 float4

#define K12_BLOCKS (EMBED / 8)  // 64 CTAs, 8 warps each -> one e per warp

// Scratch (device global — allocation-free per harness rules)
__device__ float g_o[EMBED];

// ---------------------------------------------------------------------------
// Fused K1+K2: each CTA computes z (redundantly), the full h in shared,
// then warp w computes o[e] for e = blockIdx*8 + w.
// ---------------------------------------------------------------------------
__global__ void k_fused_h_o(const float* __restrict__ U_re,
                            const float* __restrict__ U_im,
                            const float* __restrict__ W1,
                            const float* __restrict__ b1,
                            const float* __restrict__ W2,
                            const float* __restrict__ b2)
{
    __shared__ float4 sh4[FFN / 4];    // full h, 8 KB
    __shared__ float  part[NQ][NQ];    // [warp][qubit] partials
    __shared__ float  sz[NQ];

    const int t    = threadIdx.x;      // 0..255
    const int lane = t & 31;
    const int warp = t >> 5;           // 0..7

    // ---- z: thread t owns amplitude t of |psi> = U[:,0] (row stride DIM) ----
    const float re = __ldg(&U_re[t * DIM]);
    const float im = __ldg(&U_im[t * DIM]);
    const float p  = re * re + im * im;

    #pragma unroll
    for (int q = 0; q < NQ; ++q) {
        const int bit = (NQ - 1) - q;  // axis 0 of (2,)*8 is the MSB
        float v = ((t >> bit) & 1) ? -p : p;
        #pragma unroll
        for (int off = 16; off > 0; off >>= 1)
            v += __shfl_xor_sync(0xFFFFFFFFu, v, off);
        if (lane == 0) part[warp][q] = v;
    }
    __syncthreads();

    if (t < NQ) {
        float s = 0.f;
        #pragma unroll
        for (int w = 0; w < NQ; ++w) s += part[w][t];
        sz[t] = s;
    }
    __syncthreads();

    const float z0 = sz[0], z1 = sz[1], z2 = sz[2], z3 = sz[3];
    const float z4 = sz[4], z5 = sz[5], z6 = sz[6], z7 = sz[7];

    // ---- h: thread t computes 8 consecutive rows f = t*8 .. t*8+7 ----
    {
        const float4* __restrict__ w1v = (const float4*)(W1 + t * 8 * NQ);
        const float4  bb0 = __ldg((const float4*)(b1 + t * 8));
        const float4  bb1 = __ldg((const float4*)(b1 + t * 8 + 4));
        const float   bias[8] = { bb0.x, bb0.y, bb0.z, bb0.w,
                                  bb1.x, bb1.y, bb1.z, bb1.w };
        float hv[8];
        #pragma unroll
        for (int k = 0; k < 8; ++k) {
            const float4 a = __ldg(&w1v[k * 2]);
            const float4 b = __ldg(&w1v[k * 2 + 1]);
            float acc = bias[k];
            acc += z0*a.x + z1*a.y + z2*a.z + z3*a.w;
            acc += z4*b.x + z5*b.y + z6*b.z + z7*b.w;
            hv[k] = fmaxf(acc, 0.f);
        }
        sh4[t * 2]     = make_float4(hv[0], hv[1], hv[2], hv[3]);
        sh4[t * 2 + 1] = make_float4(hv[4], hv[5], hv[6], hv[7]);
    }
    __syncthreads();

    // ---- o: warp w computes e = blockIdx*8 + w ----
    const int e = blockIdx.x * 8 + warp;
    const float4* __restrict__ w2v = (const float4*)(W2 + (size_t)e * FFN);

    float acc = 0.f;
    #pragma unroll
    for (int i = lane; i < FFN / 4; i += 32) {
        const float4 w = __ldg(&w2v[i]);
        const float4 h = sh4[i];
        acc += w.x*h.x + w.y*h.y + w.z*h.z + w.w*h.w;
    }
    #pragma unroll
    for (int off = 16; off > 0; off >>= 1)
        acc += __shfl_xor_sync(0xFFFFFFFFu, acc, off);

    if (lane == 0) g_o[e] = acc + __ldg(&b2[e]);
}

// ---------------------------------------------------------------------------
// K3: broadcast o[512] into out (BS rows). Pure STG.128 streaming.
//     stride is a multiple of 128 f4-slots -> column index loop-invariant.
// ---------------------------------------------------------------------------
__global__ void k_broadcast(float4* __restrict__ out)
{
    __shared__ float4 so[EMBED / 4];
    if (threadIdx.x < EMBED / 4)
        so[threadIdx.x] = ((const float4*)g_o)[threadIdx.x];
    __syncthreads();

    unsigned idx    = blockIdx.x * blockDim.x + threadIdx.x;
    const unsigned stride = gridDim.x * blockDim.x;   // multiple of 128
    const float4 v = so[idx & (EMBED / 4 - 1)];

    for (; idx < OUT_F4; idx += stride)
        out[idx] = v;
}

// ---------------------------------------------------------------------------
extern "C" void kernel_launch(void* const* d_in, const int* in_sizes, int n_in,
                              void* d_out, int out_size)
{
    // metadata order: x, U_re, U_im, W1, b1, W2, b2  (x unused by the math)
    const float* U_re = (const float*)d_in[1];
    const float* U_im = (const float*)d_in[2];
    const float* W1   = (const float*)d_in[3];
    const float* b1   = (const float*)d_in[4];
    const float* W2   = (const float*)d_in[5];
    const float* b2   = (const float*)d_in[6];
    float*       out  = (float*)d_out;

    k_fused_h_o<<<K12_BLOCKS, 256>>>(U_re, U_im, W1, b1, W2, b2);
    // 148 SMs x 8 blocks -> full store-path occupancy, ~14 strided iters/thread
    k_broadcast<<<1184, 256>>>((float4*)out);
}